// round 15
// baseline (speedup 1.0000x reference)
#include <cuda_runtime.h>
#include <cuda_fp16.h>
#include <stdint.h>
#include <math.h>

// Problem constants
#define B_    32
#define T_    512
#define C_    1024
#define H_    16
#define D_    64
#define M_TOT (B_ * T_)          // 16384
#define N_QKV (3 * C_)           // 3072
#define NEG_BIG (-1.0e30f)

// Scratch (device globals: no allocations allowed)
__device__ __half g_qh[B_ * H_ * T_ * D_];   // [B,H,T,D], D kperm32
__device__ __half g_kh[B_ * H_ * T_ * D_];   // [B,H,T,D], D kperm32
__device__ __half g_vth[B_ * H_ * D_ * T_];  // [B,H,D,T], T kperm32 (V^T)
__device__ __half g_atth[M_TOT * C_];        // attention out, fp16, kperm32 cols
__device__ __half g_xh[M_TOT * C_];          // fp16 x, kperm32 cols
__device__ __half g_wqkvth[N_QKV * C_];      // fp16 w_qkv^T [N][K], kperm32
__device__ __half g_woutth[C_ * C_];         // fp16 w_out^T [N][K], kperm32

// fp16 k-permutation within 32-element blocks: position 8t + {0..7} holds
// cols {2t,2t+1, 2t+8,2t+9, 16+2t,16+2t+1, 16+2t+8,16+2t+9} so one LDS.128
// (8 fp16) = per-row mma fragment halves for BOTH k16 steps of a k32 block.
__device__ __host__ __forceinline__ int kperm32(int c) {   // c in [0,32)
    return 8 * ((c >> 1) & 3) + 4 * ((c >> 4) & 1) + 2 * ((c >> 3) & 1) + (c & 1);
}
__device__ __host__ __forceinline__ int kpermg(int c) {    // global col
    return (c & ~31) | kperm32(c & 31);
}

// ---------------------------------------------------------------------------
// Helpers
// ---------------------------------------------------------------------------
__device__ __forceinline__ uint32_t smem_u32(const void* p) {
    return (uint32_t)__cvta_generic_to_shared(p);
}
__device__ __forceinline__ void cp_async16(uint32_t dst, const void* src) {
    asm volatile("cp.async.cg.shared.global [%0], [%1], 16;\n" :: "r"(dst), "l"(src));
}
__device__ __forceinline__ void cp_commit() {
    asm volatile("cp.async.commit_group;\n" ::);
}
__device__ __forceinline__ void cp_wait0() {
    asm volatile("cp.async.wait_group 0;\n" ::);
}

__device__ __forceinline__ void mma_f16(float* c,
                                        uint32_t a0, uint32_t a1, uint32_t a2, uint32_t a3,
                                        uint32_t b0, uint32_t b1) {
    asm volatile(
        "mma.sync.aligned.m16n8k16.row.col.f32.f16.f16.f32 "
        "{%0,%1,%2,%3}, {%4,%5,%6,%7}, {%8,%9}, {%0,%1,%2,%3};\n"
        : "+f"(c[0]), "+f"(c[1]), "+f"(c[2]), "+f"(c[3])
        : "r"(a0), "r"(a1), "r"(a2), "r"(a3), "r"(b0), "r"(b1));
}

__device__ __forceinline__ uint32_t pack_h2(float lo, float hi) {
    __half2 h = __floats2half2_rn(lo, hi);
    return *(uint32_t*)&h;
}

// ---------------------------------------------------------------------------
// cvt x -> fp16, kperm32 columns
// ---------------------------------------------------------------------------
__global__ __launch_bounds__(256) void cvt_x_kernel(const float* __restrict__ in)
{
    int i = blockIdx.x * blockDim.x + threadIdx.x;   // float4 id
    float4 v = ((const float4*)in)[i];
    int row = i >> 8;                 // 256 float4 per row of C_=1024
    int c   = (i & 255) * 4;
    __half* orow = g_xh + (size_t)row * C_;
    *(__half2*)(orow + kpermg(c))     = __floats2half2_rn(v.x, v.y);
    *(__half2*)(orow + kpermg(c + 2)) = __floats2half2_rn(v.z, v.w);
}

// ---------------------------------------------------------------------------
// cvt + transpose: W[K][N] -> Wt[N][K] fp16 kperm32
// ---------------------------------------------------------------------------
__global__ __launch_bounds__(256) void cvt_wt_kernel(
    const float* __restrict__ in, __half* __restrict__ outp, int K, int N)
{
    __shared__ float sm[32][33];
    const int tx = threadIdx.x & 31;
    const int ty = threadIdx.x >> 5;
    const int k0 = blockIdx.x * 32;
    const int n0 = blockIdx.y * 32;
#pragma unroll
    for (int i = 0; i < 4; i++) {
        int k = ty + i * 8;
        sm[k][tx] = in[(size_t)(k0 + k) * N + n0 + tx];
    }
    __syncthreads();
#pragma unroll
    for (int i = 0; i < 4; i++) {
        int n = ty + i * 8;
        outp[(size_t)(n0 + n) * K + k0 + kperm32(tx)] = __float2half_rn(sm[tx][n]);
    }
}

// ---------------------------------------------------------------------------
// FP16 tensor-core GEMM (R10 proven): out = A[M,K] @ Wt[N,K]^T + bias
// CTA 128x128, kTile 64, 2-stage cp.async, fp16 smem rows stride 96.
// EPI==1: epilogue writes fp16 g_qh/g_kh (D kperm32) and g_vth (V^T, T kperm32)
// EPI==0: writes fp32 out[M][N]
// ---------------------------------------------------------------------------
#define SROWH 96
#define STGH  (128 * SROWH)                  // halfs per stage per array
#define GEMM_SMEM (4 * STGH * 2)             // bytes

template <int EPI, int N, int K>
__global__ __launch_bounds__(256, 2) void tgemm_kernel(
    const __half* __restrict__ Wt,
    const float* __restrict__ bias,
    float* __restrict__ out)
{
    extern __shared__ __half hsm[];
    __half* As = hsm;             // [2][STGH]
    __half* Bs = hsm + 2 * STGH;  // [2][STGH]

    const __half* A = (EPI == 1) ? g_xh : g_atth;

    const int tid  = threadIdx.x;
    const int bx   = blockIdx.x;
    const int by   = blockIdx.y;
    const int warp = tid >> 5;
    const int lane = tid & 31;
    const int g    = lane >> 2;
    const int tig  = lane & 3;
    const int wm   = warp >> 2;
    const int wn   = warp & 3;

    const int prow = tid >> 3;                // 0..31
    const int pch  = (tid & 7) * 8;
    const __half* ag = A  + ((size_t)(by * 128 + prow)) * K + pch;
    const __half* bg = Wt + ((size_t)(bx * 128 + prow)) * K + pch;
    const uint32_t a_dst = smem_u32(&As[prow * SROWH + pch]);
    const uint32_t b_dst = smem_u32(&Bs[prow * SROWH + pch]);

    float acc[4][4][4];
#pragma unroll
    for (int mt = 0; mt < 4; mt++)
#pragma unroll
        for (int nt = 0; nt < 4; nt++)
#pragma unroll
            for (int e = 0; e < 4; e++) acc[mt][nt][e] = 0.0f;

    auto load_stage = [&](int s, int k0) {
        const uint32_t sb = (uint32_t)(s * STGH * 2);
#pragma unroll
        for (int i = 0; i < 4; i++) {        // rows prow + 32*i -> 0..127
            cp_async16(a_dst + sb + i * (32 * SROWH * 2), ag + k0 + (size_t)i * (32 * K));
            cp_async16(b_dst + sb + i * (32 * SROWH * 2), bg + k0 + (size_t)i * (32 * K));
        }
        cp_commit();
    };

    load_stage(0, 0);
    int stage = 0;

#pragma unroll 1
    for (int k0 = 0; k0 < K; k0 += 64) {
        cp_wait0();
        __syncthreads();
        if (k0 + 64 < K) load_stage(stage ^ 1, k0 + 64);

        const __half* as = As + stage * STGH;
        const __half* bs = Bs + stage * STGH;

#pragma unroll
        for (int blk = 0; blk < 2; blk++) {
            const int kb = blk * 32 + tig * 8;
            uint4 aLo[4], aHi[4];
#pragma unroll
            for (int mt = 0; mt < 4; mt++) {
                int r0 = wm * 64 + mt * 16 + g;
                aLo[mt] = *(const uint4*)&as[r0 * SROWH + kb];
                aHi[mt] = *(const uint4*)&as[(r0 + 8) * SROWH + kb];
            }
            uint4 bW[4];
#pragma unroll
            for (int nt = 0; nt < 4; nt++) {
                int col = wn * 32 + nt * 8 + g;
                bW[nt] = *(const uint4*)&bs[col * SROWH + kb];
            }
#pragma unroll
            for (int mt = 0; mt < 4; mt++) {
#pragma unroll
                for (int nt = 0; nt < 4; nt++) {
                    mma_f16(acc[mt][nt], aLo[mt].x, aHi[mt].x, aLo[mt].y, aHi[mt].y,
                            bW[nt].x, bW[nt].y);
                    mma_f16(acc[mt][nt], aLo[mt].z, aHi[mt].z, aLo[mt].w, aHi[mt].w,
                            bW[nt].z, bW[nt].w);
                }
            }
        }
        stage ^= 1;
    }

    // Epilogue: pairs (e0,e1) = (row r, n..n+1), (e2,e3) = (row r+8, n..n+1)
#pragma unroll
    for (int mt = 0; mt < 4; mt++) {
#pragma unroll
        for (int nt = 0; nt < 4; nt++) {
            int r0   = by * 128 + wm * 64 + mt * 16 + g;
            int n    = bx * 128 + wn * 32 + nt * 8 + 2 * tig;
            float v0 = acc[mt][nt][0] + bias[n];
            float v1 = acc[mt][nt][1] + bias[n + 1];
            float v2 = acc[mt][nt][2] + bias[n];
            float v3 = acc[mt][nt][3] + bias[n + 1];
            if (EPI == 1) {
                int sec = n >> 10;
                int c   = n & 1023;
                int h   = c >> 6;
                int d   = c & 63;
                int b0  = r0 >> 9, t0 = r0 & 511;
                int b1  = (r0 + 8) >> 9, t1 = (r0 + 8) & 511;
                if (sec < 2) {
                    __half* dst = (sec == 0) ? g_qh : g_kh;
                    int dp = kpermg(d);
                    *(__half2*)&dst[((size_t)(b0 * H_ + h) * T_ + t0) * D_ + dp] =
                        __floats2half2_rn(v0, v1);
                    *(__half2*)&dst[((size_t)(b1 * H_ + h) * T_ + t1) * D_ + dp] =
                        __floats2half2_rn(v2, v3);
                } else {
                    // V^T: [B,H,D,T], T kperm32
                    int tp0 = kpermg(t0), tp1 = kpermg(t1);
                    size_t base = (size_t)(b0 * H_ + h) * D_;
                    g_vth[(base + d)     * T_ + tp0] = __float2half_rn(v0);
                    g_vth[(base + d + 1) * T_ + tp0] = __float2half_rn(v1);
                    size_t base1 = (size_t)(b1 * H_ + h) * D_;
                    g_vth[(base1 + d)     * T_ + tp1] = __float2half_rn(v2);
                    g_vth[(base1 + d + 1) * T_ + tp1] = __float2half_rn(v3);
                }
            } else {
                out[(size_t)r0 * N + n]           = v0;
                out[(size_t)r0 * N + n + 1]       = v1;
                out[(size_t)(r0 + 8) * N + n]     = v2;
                out[(size_t)(r0 + 8) * N + n + 1] = v3;
            }
        }
    }
}

// ---------------------------------------------------------------------------
// FP16 mma causal flash attention.
// CTA: 128 threads (4 warps), 64 query rows; warp owns 16 rows.
// Staging (128 threads): 64 rows x 8 chunks = 512 chunks, 16 rows per iter.
// ---------------------------------------------------------------------------
#define AS_S 96   // smem stride in halfs (192B rows; conflict-free for uint4)
#define ATTN_SMEM (3 * 64 * AS_S * 2)

__global__ __launch_bounds__(128) void attn_f16_kernel()
{
    extern __shared__ __half ash[];
    __half* Qs = ash;
    __half* Kt = ash + 64 * AS_S;
    __half* Vt = ash + 2 * 64 * AS_S;

    const int tid  = threadIdx.x;
    const int w    = tid >> 5;
    const int lane = tid & 31;
    const int g    = lane >> 2;
    const int tig  = lane & 3;
    const int qt   = blockIdx.x;
    const int bh   = blockIdx.y;
    const int b    = bh >> 4;
    const int h    = bh & 15;

    const __half* Qg = g_qh  + (size_t)bh * T_ * D_;
    const __half* Kg = g_kh  + (size_t)bh * T_ * D_;
    const __half* Vg = g_vth + (size_t)bh * D_ * T_;

    const int r0 = qt * 64 + w * 16 + g;   // global q row (lower 8-group)
    const int r1 = r0 + 8;

    const int rch = tid >> 3;              // 0..15
    const int cc  = (tid & 7) * 8;         // 0..56

    // Stage Q tile: rows rch + 16*i (i<4) -> 0..63
    {
        uint32_t qdst = smem_u32(&Qs[rch * AS_S + cc]);
#pragma unroll
        for (int i = 0; i < 4; i++) {
            int r = rch + 16 * i;
            cp_async16(qdst + i * (16 * AS_S * 2),
                       Qg + (size_t)(qt * 64 + r) * D_ + cc);
        }
        cp_commit();
    }
    cp_wait0();
    __syncthreads();

    // Q fragments (held in registers for the whole loop)
    uint4 qlo[2], qhi[2];
#pragma unroll
    for (int blk = 0; blk < 2; blk++) {
        qlo[blk] = *(const uint4*)&Qs[(w * 16 + g) * AS_S + blk * 32 + tig * 8];
        qhi[blk] = *(const uint4*)&Qs[(w * 16 + g + 8) * AS_S + blk * 32 + tig * 8];
    }

    float oacc[8][4];
#pragma unroll
    for (int nt = 0; nt < 8; nt++)
#pragma unroll
        for (int e = 0; e < 4; e++) oacc[nt][e] = 0.0f;
    float m0 = NEG_BIG, m1 = NEG_BIG, l0 = 0.0f, l1 = 0.0f;

    const uint32_t kdst = smem_u32(&Kt[rch * AS_S + cc]);
    const uint32_t vdst = smem_u32(&Vt[rch * AS_S + cc]);

    for (int jt = 0; jt <= qt; jt++) {
        __syncthreads();    // previous-iteration consumers done with Kt/Vt
        // Stage K tile (rows=keys 0..63) and V^T tile (rows=d 0..63)
#pragma unroll
        for (int i = 0; i < 4; i++) {
            int r = rch + 16 * i;
            cp_async16(kdst + i * (16 * AS_S * 2),
                       Kg + (size_t)(jt * 64 + r) * D_ + cc);
            cp_async16(vdst + i * (16 * AS_S * 2),
                       Vg + (size_t)r * T_ + jt * 64 + cc);
        }
        cp_commit();
        cp_wait0();
        __syncthreads();

        // S = Q K^T  (16 x 64 per warp)
        float cfr[8][4];
#pragma unroll
        for (int nt = 0; nt < 8; nt++)
#pragma unroll
            for (int e = 0; e < 4; e++) cfr[nt][e] = 0.0f;
#pragma unroll
        for (int blk = 0; blk < 2; blk++) {
#pragma unroll
            for (int nt = 0; nt < 8; nt++) {
                uint4 kb = *(const uint4*)&Kt[(nt * 8 + g) * AS_S + blk * 32 + tig * 8];
                mma_f16(cfr[nt], qlo[blk].x, qhi[blk].x, qlo[blk].y, qhi[blk].y,
                        kb.x, kb.y);
                mma_f16(cfr[nt], qlo[blk].z, qhi[blk].z, qlo[blk].w, qhi[blk].w,
                        kb.z, kb.w);
            }
        }
        // scale 1/sqrt(D)
#pragma unroll
        for (int nt = 0; nt < 8; nt++)
#pragma unroll
            for (int e = 0; e < 4; e++) cfr[nt][e] *= 0.125f;

        // causal mask on diagonal tile
        if (jt == qt) {
#pragma unroll
            for (int nt = 0; nt < 8; nt++) {
                int jc = jt * 64 + nt * 8 + 2 * tig;
                if (jc     > r0) cfr[nt][0] = NEG_BIG;
                if (jc + 1 > r0) cfr[nt][1] = NEG_BIG;
                if (jc     > r1) cfr[nt][2] = NEG_BIG;
                if (jc + 1 > r1) cfr[nt][3] = NEG_BIG;
            }
        }

        // online softmax
        float mx0 = NEG_BIG, mx1 = NEG_BIG;
#pragma unroll
        for (int nt = 0; nt < 8; nt++) {
            mx0 = fmaxf(mx0, fmaxf(cfr[nt][0], cfr[nt][1]));
            mx1 = fmaxf(mx1, fmaxf(cfr[nt][2], cfr[nt][3]));
        }
        mx0 = fmaxf(mx0, __shfl_xor_sync(0xffffffffu, mx0, 1));
        mx0 = fmaxf(mx0, __shfl_xor_sync(0xffffffffu, mx0, 2));
        mx1 = fmaxf(mx1, __shfl_xor_sync(0xffffffffu, mx1, 1));
        mx1 = fmaxf(mx1, __shfl_xor_sync(0xffffffffu, mx1, 2));
        float mn0 = fmaxf(m0, mx0), mn1 = fmaxf(m1, mx1);
        float cr0 = __expf(m0 - mn0), cr1 = __expf(m1 - mn1);
        l0 *= cr0; l1 *= cr1;
#pragma unroll
        for (int nt = 0; nt < 8; nt++) {
            oacc[nt][0] *= cr0; oacc[nt][1] *= cr0;
            oacc[nt][2] *= cr1; oacc[nt][3] *= cr1;
        }

        // exp -> P fragments (c-layout == a-layout; no smem round trip)
        uint32_t pa0[4], pa1[4], pa2[4], pa3[4];   // per k16 step ks
#pragma unroll
        for (int ks = 0; ks < 4; ks++) {
            float p00 = __expf(cfr[2 * ks][0] - mn0);
            float p01 = __expf(cfr[2 * ks][1] - mn0);
            float p02 = __expf(cfr[2 * ks][2] - mn1);
            float p03 = __expf(cfr[2 * ks][3] - mn1);
            float p10 = __expf(cfr[2 * ks + 1][0] - mn0);
            float p11 = __expf(cfr[2 * ks + 1][1] - mn0);
            float p12 = __expf(cfr[2 * ks + 1][2] - mn1);
            float p13 = __expf(cfr[2 * ks + 1][3] - mn1);
            l0 += p00 + p01 + p10 + p11;
            l1 += p02 + p03 + p12 + p13;
            pa0[ks] = pack_h2(p00, p01);
            pa1[ks] = pack_h2(p02, p03);
            pa2[ks] = pack_h2(p10, p11);
            pa3[ks] = pack_h2(p12, p13);
        }
        m0 = mn0; m1 = mn1;

        // O += P V   (B from V^T tile)
#pragma unroll
        for (int blk = 0; blk < 2; blk++) {
#pragma unroll
            for (int nt = 0; nt < 8; nt++) {
                uint4 vb = *(const uint4*)&Vt[(nt * 8 + g) * AS_S + blk * 32 + tig * 8];
                mma_f16(oacc[nt], pa0[2 * blk], pa1[2 * blk], pa2[2 * blk], pa3[2 * blk],
                        vb.x, vb.y);
                mma_f16(oacc[nt], pa0[2 * blk + 1], pa1[2 * blk + 1],
                        pa2[2 * blk + 1], pa3[2 * blk + 1], vb.z, vb.w);
            }
        }
    }

    // finalize: reduce l over tig quad, normalize, write fp16 kperm32 g_atth
    l0 += __shfl_xor_sync(0xffffffffu, l0, 1);
    l0 += __shfl_xor_sync(0xffffffffu, l0, 2);
    l1 += __shfl_xor_sync(0xffffffffu, l1, 1);
    l1 += __shfl_xor_sync(0xffffffffu, l1, 2);
    float i0 = 1.0f / l0, i1 = 1.0f / l1;

    __half* out0 = g_atth + (size_t)(b * T_ + r0) * C_ + h * 64;
    __half* out1 = g_atth + (size_t)(b * T_ + r1) * C_ + h * 64;
#pragma unroll
    for (int nt = 0; nt < 8; nt++) {
        int pc = nt * 8 + 2 * tig;
        int pp = kpermg(pc);
        *(__half2*)(out0 + pp) = __floats2half2_rn(oacc[nt][0] * i0, oacc[nt][1] * i0);
        *(__half2*)(out1 + pp) = __floats2half2_rn(oacc[nt][2] * i1, oacc[nt][3] * i1);
    }
}

// ---------------------------------------------------------------------------
// Launch
// ---------------------------------------------------------------------------
extern "C" void kernel_launch(void* const* d_in, const int* in_sizes, int n_in,
                              void* d_out, int out_size)
{
    const float* x     = (const float*)d_in[0];
    const float* w_qkv = (const float*)d_in[1];
    const float* b_qkv = (const float*)d_in[2];
    const float* w_out = (const float*)d_in[3];
    const float* b_out = (const float*)d_in[4];
    float* out = (float*)d_out;

    cudaFuncSetAttribute(attn_f16_kernel,
                         cudaFuncAttributeMaxDynamicSharedMemorySize, ATTN_SMEM);
    cudaFuncSetAttribute(tgemm_kernel<1, N_QKV, C_>,
                         cudaFuncAttributeMaxDynamicSharedMemorySize, GEMM_SMEM);
    cudaFuncSetAttribute(tgemm_kernel<0, C_, C_>,
                         cudaFuncAttributeMaxDynamicSharedMemorySize, GEMM_SMEM);

    __half* wqkvt; cudaGetSymbolAddress((void**)&wqkvt, g_wqkvth);
    __half* woutt; cudaGetSymbolAddress((void**)&woutt, g_woutth);

    // 0) fp16 + permute/transpose prep
    {
        int n4x = (M_TOT * C_) / 4;
        cvt_x_kernel<<<n4x / 256, 256>>>(x);
        dim3 g1(C_ / 32, N_QKV / 32);
        cvt_wt_kernel<<<g1, 256>>>(w_qkv, wqkvt, C_, N_QKV);
        dim3 g2(C_ / 32, C_ / 32);
        cvt_wt_kernel<<<g2, 256>>>(w_out, woutt, C_, C_);
    }
    // 1) QKV projection + bias -> g_qh/g_kh (fp16) and g_vth (V^T fp16)
    {
        dim3 grid(N_QKV / 128, M_TOT / 128);  // (24, 128)
        tgemm_kernel<1, N_QKV, C_><<<grid, 256, GEMM_SMEM>>>(wqkvt, b_qkv, nullptr);
    }
    // 2) Causal flash attention (fp16 mma) -> g_atth (fp16, kperm32)
    {
        dim3 grid(T_ / 64, B_ * H_);          // (8, 512)
        attn_f16_kernel<<<grid, 128, ATTN_SMEM>>>();
    }
    // 3) Output projection + bias -> d_out
    {
        dim3 grid(C_ / 128, M_TOT / 128);     // (8, 128)
        tgemm_kernel<0, C_, C_><<<grid, 256, GEMM_SMEM>>>(woutt, b_out, out);
    }
}